// round 13
// baseline (speedup 1.0000x reference)
#include <cuda_runtime.h>
#include <cuda_bf16.h>
#include <math.h>

#define BB   1024
#define FF   257
#define CC   32
#define QKV  96
#define QSP  100               // padded qs row stride
#define NROWS (BB*FF)          // 263168

typedef unsigned long long ull;

// ---------------- scratch (device globals; allocation-free) ----------------
__device__ float g_h  [(size_t)NROWS*CC];   // layer-0 input activations
__device__ float g_c  [(size_t)NROWS*CC];   // conv output per layer
__device__ float g_att[(size_t)NROWS*CC];   // attention branch per layer
__device__ float g_part[BB*64];             // per-CTA BN partial sums
__device__ float g_stats[64];               // BN scale[32], shift[32]

__device__ __forceinline__ float gelu_exact(float v) {
    return 0.5f * v * (1.0f + erff(v * 0.70710678118654752f));
}
// 8-lane butterfly reduction with an explicit subgroup mask.
__device__ __forceinline__ float red8(float v, unsigned mask) {
    v += __shfl_xor_sync(mask, v, 1);
    v += __shfl_xor_sync(mask, v, 2);
    v += __shfl_xor_sync(mask, v, 4);
    return v;
}
// Blackwell packed fp32x2 FMA (PTX-only; 2x fp32 throughput).
__device__ __forceinline__ ull ffma2(ull a, ull b, ull c) {
    ull d;
    asm("fma.rn.f32x2 %0, %1, %2, %3;" : "=l"(d) : "l"(a), "l"(b), "l"(c));
    return d;
}
__device__ __forceinline__ ull pack2(float lo, float hi) {
    ull d; asm("mov.b64 %0, {%1, %2};" : "=l"(d) : "f"(lo), "f"(hi)); return d;
}
__device__ __forceinline__ float unpack_sum(ull v) {
    float lo, hi; asm("mov.b64 {%0, %1}, %2;" : "=f"(lo), "=f"(hi) : "l"(v));
    return lo + hi;
}

// ---------------- input projection: (B,F,18) @ (18,32) + b ----------------
#define INP_SMEM_FLOATS (576 + 32 + 256*19 + 256*33)
#define INP_SMEM_BYTES  (INP_SMEM_FLOATS*4)
__global__ __launch_bounds__(256) void input_proj(const float* __restrict__ x,
                                                  const float* __restrict__ in_w,
                                                  const float* __restrict__ in_b) {
    extern __shared__ float sm[];
    float* w  = sm;             // 18*32
    float* bv = w + 576;        // 32
    float* sx = bv + 32;        // 256*19 (pad 19)
    float* ys = sx + 256*19;    // 256*33 (pad 33)
    int t = threadIdx.x;
    for (int i = t; i < 576; i += 256) w[i] = in_w[i];
    if (t < 32) bv[t] = in_b[t];

    size_t base = (size_t)blockIdx.x * 256;
    const float* xg = x + base * 18;
    for (int i = t; i < 256*18; i += 256) sx[(i/18)*19 + (i%18)] = xg[i];
    __syncthreads();

    const float* xr = sx + t*19;
    float acc[32];
    #pragma unroll
    for (int co = 0; co < 32; co++) acc[co] = bv[co];
    #pragma unroll
    for (int i = 0; i < 18; i++) {
        float xv = xr[i];
        #pragma unroll
        for (int co = 0; co < 32; co++) acc[co] += xv * w[i*32 + co];
    }
    #pragma unroll
    for (int co = 0; co < 32; co++) ys[t*33 + co] = acc[co];
    __syncthreads();
    float* og = g_h + base * 32;
    for (int i = t; i < 256*32; i += 256) og[i] = ys[(i >> 5)*33 + (i & 31)];
}

// ---------------- per-layer heavy kernel (512 thr) ----------
#define PRE_SMEM_FLOATS ((FF+2)*CC + FF*QSP + 3*CC*CC + CC*QKV + CC*CC + CC + 64 + 64 + 1024)
#define PRE_SMEM_BYTES  (PRE_SMEM_FLOATS*4)

__global__ __launch_bounds__(512, 1) void layer_pre(const float* __restrict__ conv_w,
                                                    const float* __restrict__ qkv_w,
                                                    const float* __restrict__ proj_w,
                                                    const float* __restrict__ proj_b,
                                                    const float* __restrict__ ln_g,
                                                    const float* __restrict__ ln_b,
                                                    int l) {
    extern __shared__ float sm[];
    float* hp  = sm;                       // (FF+2)*32 padded activations
    float* qs  = hp + (FF+2)*CC;           // FF*QSP
    float* cw  = qs + FF*QSP;              // 3072
    float* qw  = cw + 3*CC*CC;             // 3072
    float* pw  = qw + CC*QKV;              // 1024
    float* pb  = pw + CC*CC;               // 32
    float* st  = pb + CC;                  // 64
    float* lgb = st + 64;                  // 64
    float* red = lgb + 64;                 // 1024

    const int b = blockIdx.x;
    const int t = threadIdx.x;

    // -------- weights + params --------
    for (int i = t; i < 3*CC*CC; i += 512) cw[i] = conv_w[l*3*CC*CC + i];
    for (int i = t; i < CC*QKV;  i += 512) qw[i] = qkv_w[l*CC*QKV + i];
    for (int i = t; i < CC*CC;   i += 512) pw[i] = proj_w[l*CC*CC + i];
    if (t < CC) pb[t] = proj_b[l*CC + t];
    if (l > 0) {
        if (t >= 64 && t < 128) st[t-64] = g_stats[t-64];
        if (t >= 128 && t < 160) lgb[t-128]      = ln_g[(l-1)*32 + (t-128)];
        if (t >= 160 && t < 192) lgb[32+(t-160)] = ln_b[(l-1)*32 + (t-160)];
    }
    if (t < CC) { hp[t] = 0.f; hp[(FF+1)*CC + t] = 0.f; }   // conv pad rows
    __syncthreads();

    // -------- load h into hp (fused post of layer l-1 when l>0) --------
    if (l == 0) {
        const float4* hrow = (const float4*)(g_h + (size_t)b * FF * CC);
        float4* hpd = (float4*)(hp + CC);
        for (int i = t; i < FF*8; i += 512) hpd[i] = hrow[i];
    } else {
        const float* cg0 = g_c   + (size_t)b * FF * CC;
        const float* ag0 = g_att + (size_t)b * FF * CC;
        int grp = t >> 3, ln8 = t & 7;
        int c0 = ln8 * 4;
        unsigned gmask = 0xffu << ((t & 31) & 24);   // 8-lane subgroup mask
        float s0 = st[c0], s1 = st[c0+1], s2 = st[c0+2], s3 = st[c0+3];
        float h0 = st[32+c0], h1 = st[32+c0+1], h2 = st[32+c0+2], h3 = st[32+c0+3];
        float lg0 = lgb[c0], lg1 = lgb[c0+1], lg2 = lgb[c0+2], lg3 = lgb[c0+3];
        float lb0 = lgb[32+c0], lb1 = lgb[32+c0+1], lb2 = lgb[32+c0+2], lb3 = lgb[32+c0+3];
        for (int f = grp; f < FF; f += 64) {
            float4 c4 = *(const float4*)(cg0 + f*32 + c0);
            float4 a4 = *(const float4*)(ag0 + f*32 + c0);
            float v0 = gelu_exact(c4.x*s0 + h0) + a4.x;
            float v1 = gelu_exact(c4.y*s1 + h1) + a4.y;
            float v2 = gelu_exact(c4.z*s2 + h2) + a4.z;
            float v3 = gelu_exact(c4.w*s3 + h3) + a4.w;
            float mean = red8(v0+v1+v2+v3, gmask) * (1.f/32.f);
            float sq   = red8(v0*v0+v1*v1+v2*v2+v3*v3, gmask) * (1.f/32.f);
            float r = rsqrtf(sq - mean*mean + 1e-5f);
            float4 o;
            o.x = (v0-mean)*r*lg0 + lb0;
            o.y = (v1-mean)*r*lg1 + lb1;
            o.z = (v2-mean)*r*lg2 + lb2;
            o.w = (v3-mean)*r*lg3 + lb3;
            *(float4*)(hp + (f+1)*32 + c0) = o;
        }
    }
    __syncthreads();

    // -------- conv (width 3, SAME): 2 consecutive f per warp iteration -----
    {
        const int co = t & 31;
        const int fg = t >> 5;             // 16 warps
        ull w0p[16], w1p[16], w2p[16];
        #pragma unroll
        for (int j = 0; j < 16; j++) {
            w0p[j] = pack2(cw[       (2*j)*32 + co], cw[       (2*j+1)*32 + co]);
            w1p[j] = pack2(cw[1024 + (2*j)*32 + co], cw[1024 + (2*j+1)*32 + co]);
            w2p[j] = pack2(cw[2048 + (2*j)*32 + co], cw[2048 + (2*j+1)*32 + co]);
        }
        float ssum = 0.f, ssq = 0.f;
        float* cg = g_c + (size_t)b * FF * CC;
        for (int fp = fg; fp < 129; fp += 16) {      // f = 2*fp, 2*fp+1
            const int f = 2*fp;
            const float* r = hp + f*32;              // padded rows f-1..f+2
            ull aA0 = 0ull, aA1 = 0ull;              // output f
            ull aB0 = 0ull, aB1 = 0ull;              // output f+1
            #pragma unroll
            for (int q4 = 0; q4 < 8; q4++) {
                ulonglong2 m0 = *(const ulonglong2*)(r +      q4*4);
                ulonglong2 m1 = *(const ulonglong2*)(r + 32 + q4*4);
                ulonglong2 m2 = *(const ulonglong2*)(r + 64 + q4*4);
                ulonglong2 m3 = *(const ulonglong2*)(r + 96 + q4*4);
                if ((q4 & 1) == 0) {
                    aA0 = ffma2(m0.x, w0p[2*q4],   aA0);
                    aA0 = ffma2(m0.y, w0p[2*q4+1], aA0);
                    aA0 = ffma2(m1.x, w1p[2*q4],   aA0);
                    aA0 = ffma2(m1.y, w1p[2*q4+1], aA0);
                    aA0 = ffma2(m2.x, w2p[2*q4],   aA0);
                    aA0 = ffma2(m2.y, w2p[2*q4+1], aA0);
                    aB0 = ffma2(m1.x, w0p[2*q4],   aB0);
                    aB0 = ffma2(m1.y, w0p[2*q4+1], aB0);
                    aB0 = ffma2(m2.x, w1p[2*q4],   aB0);
                    aB0 = ffma2(m2.y, w1p[2*q4+1], aB0);
                    aB0 = ffma2(m3.x, w2p[2*q4],   aB0);
                    aB0 = ffma2(m3.y, w2p[2*q4+1], aB0);
                } else {
                    aA1 = ffma2(m0.x, w0p[2*q4],   aA1);
                    aA1 = ffma2(m0.y, w0p[2*q4+1], aA1);
                    aA1 = ffma2(m1.x, w1p[2*q4],   aA1);
                    aA1 = ffma2(m1.y, w1p[2*q4+1], aA1);
                    aA1 = ffma2(m2.x, w2p[2*q4],   aA1);
                    aA1 = ffma2(m2.y, w2p[2*q4+1], aA1);
                    aB1 = ffma2(m1.x, w0p[2*q4],   aB1);
                    aB1 = ffma2(m1.y, w0p[2*q4+1], aB1);
                    aB1 = ffma2(m2.x, w1p[2*q4],   aB1);
                    aB1 = ffma2(m2.y, w1p[2*q4+1], aB1);
                    aB1 = ffma2(m3.x, w2p[2*q4],   aB1);
                    aB1 = ffma2(m3.y, w2p[2*q4+1], aB1);
                }
            }
            float accA = unpack_sum(aA0) + unpack_sum(aA1);
            cg[f*32 + co] = accA;
            ssum += accA; ssq += accA*accA;
            if (f + 1 < FF) {
                float accB = unpack_sum(aB0) + unpack_sum(aB1);
                cg[(f+1)*32 + co] = accB;
                ssum += accB; ssq += accB*accB;
            }
        }
        red[      fg*32 + co] = ssum;
        red[512 + fg*32 + co] = ssq;
    }
    __syncthreads();
    if (t < 64) {
        float s = 0.f;
        int base = (t < 32) ? t : (512 + (t - 32));
        #pragma unroll
        for (int g = 0; g < 16; g++) s += red[base + g*32];
        g_part[b*64 + t] = s;
    }

    // -------- qkv: (F,32)@(32,96) — warp per row, 2 rows/iter (f, f+16) ----
    {
        const int co = t & 31;
        const int fg = t >> 5;             // 16 warps
        ull wa[16], wb[16], wc[16];
        #pragma unroll
        for (int j = 0; j < 16; j++) {
            wa[j] = pack2(qw[(2*j)*96 + co],      qw[(2*j+1)*96 + co]);
            wb[j] = pack2(qw[(2*j)*96 + co + 32], qw[(2*j+1)*96 + co + 32]);
            wc[j] = pack2(qw[(2*j)*96 + co + 64], qw[(2*j+1)*96 + co + 64]);
        }
        for (int f = fg; f < FF; f += 32) {
            const int f2 = f + 16;
            const bool has2 = f2 < FF;
            const float* r0 = hp + (f+1)*32;
            const float* r1 = hp + ((has2 ? f2 : f) + 1)*32;
            ull a0 = 0ull, b0q = 0ull, c0q = 0ull;
            ull a1 = 0ull, b1q = 0ull, c1q = 0ull;
            #pragma unroll
            for (int q4 = 0; q4 < 8; q4++) {
                ulonglong2 m0 = *(const ulonglong2*)(r0 + q4*4);
                ulonglong2 m1 = *(const ulonglong2*)(r1 + q4*4);
                a0  = ffma2(m0.x, wa[2*q4],   a0);
                a0  = ffma2(m0.y, wa[2*q4+1], a0);
                b0q = ffma2(m0.x, wb[2*q4],   b0q);
                b0q = ffma2(m0.y, wb[2*q4+1], b0q);
                c0q = ffma2(m0.x, wc[2*q4],   c0q);
                c0q = ffma2(m0.y, wc[2*q4+1], c0q);
                a1  = ffma2(m1.x, wa[2*q4],   a1);
                a1  = ffma2(m1.y, wa[2*q4+1], a1);
                b1q = ffma2(m1.x, wb[2*q4],   b1q);
                b1q = ffma2(m1.y, wb[2*q4+1], b1q);
                c1q = ffma2(m1.x, wc[2*q4],   c1q);
                c1q = ffma2(m1.y, wc[2*q4+1], c1q);
            }
            qs[f*QSP + co]      = unpack_sum(a0);
            qs[f*QSP + co + 32] = unpack_sum(b0q);
            qs[f*QSP + co + 64] = unpack_sum(c0q);
            if (has2) {
                qs[f2*QSP + co]      = unpack_sum(a1);
                qs[f2*QSP + co + 32] = unpack_sum(b1q);
                qs[f2*QSP + co + 64] = unpack_sum(c1q);
            }
        }
    }
    __syncthreads();

    // -------- banded attention (window [f, f+2]) — float4 loads ------------
    for (int idx = t; idx < FF*4; idx += 512) {
        int f  = idx >> 2;
        int hh = idx & 3;
        float4 q0 = *(const float4*)(qs + f*QSP + hh*8);
        float4 q1 = *(const float4*)(qs + f*QSP + hh*8 + 4);
        int nv = min(FF-1, f+2) - f + 1;
        float sc[3];
        float m = -1e30f;
        #pragma unroll
        for (int jj = 0; jj < 3; jj++) {
            if (jj < nv) {
                int j = f + jj;
                float4 k0 = *(const float4*)(qs + j*QSP + 32 + hh*8);
                float4 k1 = *(const float4*)(qs + j*QSP + 32 + hh*8 + 4);
                float s = q0.x*k0.x + q0.y*k0.y + q0.z*k0.z + q0.w*k0.w
                        + q1.x*k1.x + q1.y*k1.y + q1.z*k1.z + q1.w*k1.w;
                s *= 0.35355339059327373f;
                sc[jj] = s;
                m = fmaxf(m, s);
            }
        }
        float e[3]; float den = 0.f;
        #pragma unroll
        for (int jj = 0; jj < 3; jj++)
            if (jj < nv) { e[jj] = expf(sc[jj] - m); den += e[jj]; }
        float inv = 1.f / den;
        float4 o0 = make_float4(0.f,0.f,0.f,0.f);
        float4 o1 = make_float4(0.f,0.f,0.f,0.f);
        #pragma unroll
        for (int jj = 0; jj < 3; jj++) {
            if (jj < nv) {
                float wj = e[jj] * inv;
                int j = f + jj;
                float4 v0 = *(const float4*)(qs + j*QSP + 64 + hh*8);
                float4 v1 = *(const float4*)(qs + j*QSP + 64 + hh*8 + 4);
                o0.x += wj*v0.x; o0.y += wj*v0.y; o0.z += wj*v0.z; o0.w += wj*v0.w;
                o1.x += wj*v1.x; o1.y += wj*v1.y; o1.z += wj*v1.z; o1.w += wj*v1.w;
            }
        }
        *(float4*)(qs + f*QSP + hh*8)     = o0;   // overwrite q slot
        *(float4*)(qs + f*QSP + hh*8 + 4) = o1;
    }
    __syncthreads();

    // -------- output projection: (F,32)@(32,32)+b — 2 rows/iter ------------
    {
        const int co = t & 31;
        const int fg = t >> 5;             // 16 warps
        ull wp[16];
        #pragma unroll
        for (int j = 0; j < 16; j++)
            wp[j] = pack2(pw[(2*j)*32 + co], pw[(2*j+1)*32 + co]);
        float bias = pb[co];
        float* ag = g_att + (size_t)b * FF * CC;
        for (int f = fg; f < FF; f += 32) {
            const int f2 = f + 16;
            const bool has2 = f2 < FF;
            const float* r0 = qs + f*QSP;
            const float* r1 = qs + (has2 ? f2 : f)*QSP;
            ull p00 = 0ull, p01 = 0ull, p10 = 0ull, p11 = 0ull;
            #pragma unroll
            for (int q4 = 0; q4 < 8; q4++) {
                ulonglong2 m0 = *(const ulonglong2*)(r0 + q4*4);
                ulonglong2 m1 = *(const ulonglong2*)(r1 + q4*4);
                p00 = ffma2(m0.x, wp[2*q4],   p00);
                p01 = ffma2(m0.y, wp[2*q4+1], p01);
                p10 = ffma2(m1.x, wp[2*q4],   p10);
                p11 = ffma2(m1.y, wp[2*q4+1], p11);
            }
            ag[f*32 + co] = bias + unpack_sum(p00) + unpack_sum(p01);
            if (has2)
                ag[f2*32 + co] = bias + unpack_sum(p10) + unpack_sum(p11);
        }
    }
}

// ---------------- BN stats finalize (1 CTA, 1024 threads) ----------------
__global__ __launch_bounds__(1024) void bn_reduce(const float* __restrict__ bn_g,
                                                  const float* __restrict__ bn_b,
                                                  int l) {
    __shared__ float sm[1024];
    int t = threadIdx.x;
    int q = t & 63;
    int g = t >> 6;                        // 16 groups
    float s = 0.f;
    for (int b = g; b < BB; b += 16) s += g_part[b*64 + q];
    sm[t] = s;
    __syncthreads();
    if (t < 64) {
        float acc = 0.f;
        #pragma unroll
        for (int g2 = 0; g2 < 16; g2++) acc += sm[t + g2*64];
        sm[t] = acc;
    }
    __syncthreads();
    if (t < 32) {
        const float N = (float)NROWS;
        float mu  = sm[t] / N;
        float var = sm[32+t] / N - mu*mu;
        float scale = bn_g[l*32 + t] * rsqrtf(var + 1e-5f);
        g_stats[t]      = scale;
        g_stats[32 + t] = bn_b[l*32 + t] - mu*scale;
    }
}

// ---------------- fused: post(layer3) + head MLP ----------------
#define HEAD_SMEM_FLOATS (512*33 + 64 + 64 + 512 + 16 + 16 + 1)
#define HEAD_SMEM_BYTES  (HEAD_SMEM_FLOATS*4)
__global__ __launch_bounds__(512) void head_kernel(const float* __restrict__ ln_g,
                                                   const float* __restrict__ ln_b,
                                                   const float* __restrict__ h1_w,
                                                   const float* __restrict__ h1_b,
                                                   const float* __restrict__ h2_w,
                                                   const float* __restrict__ h2_b,
                                                   float* __restrict__ out) {
    extern __shared__ float sm[];
    float* ys  = sm;              // 512*33
    float* st  = ys + 512*33;     // 64
    float* lgb = st + 64;         // 64
    float* w1  = lgb + 64;        // 512
    float* b1  = w1 + 512;        // 16
    float* w2  = b1 + 16;         // 16
    float* b2s = w2 + 16;         // 1
    int t = threadIdx.x;
    if (t < 64)  st[t] = g_stats[t];
    if (t >= 64 && t < 96)   lgb[t-64]      = ln_g[3*32 + (t-64)];
    if (t >= 96 && t < 128)  lgb[32+(t-96)] = ln_b[3*32 + (t-96)];
    if (t >= 128 && t < 144) { b1[t-128] = h1_b[t-128]; w2[t-128] = h2_w[t-128]; }
    if (t == 144) b2s[0] = h2_b[0];
    for (int i = t; i < 512; i += 512) w1[i] = h1_w[i];
    __syncthreads();

    size_t base = (size_t)blockIdx.x * 512;
    const float* cg0 = g_c   + base * 32;
    const float* ag0 = g_att + base * 32;
    int grp = t >> 3, ln8 = t & 7;
    int c0 = ln8 * 4;
    unsigned gmask = 0xffu << ((t & 31) & 24);
    {
        float s0 = st[c0], s1 = st[c0+1], s2 = st[c0+2], s3 = st[c0+3];
        float h0 = st[32+c0], h1 = st[32+c0+1], h2 = st[32+c0+2], h3 = st[32+c0+3];
        float lg0 = lgb[c0], lg1 = lgb[c0+1], lg2 = lgb[c0+2], lg3 = lgb[c0+3];
        float lb0 = lgb[32+c0], lb1 = lgb[32+c0+1], lb2 = lgb[32+c0+2], lb3 = lgb[32+c0+3];
        #pragma unroll
        for (int it = 0; it < 8; it++) {
            int lr = grp + it*64;
            float4 c4 = *(const float4*)(cg0 + lr*32 + c0);
            float4 a4 = *(const float4*)(ag0 + lr*32 + c0);
            float v0 = gelu_exact(c4.x*s0 + h0) + a4.x;
            float v1 = gelu_exact(c4.y*s1 + h1) + a4.y;
            float v2 = gelu_exact(c4.z*s2 + h2) + a4.z;
            float v3 = gelu_exact(c4.w*s3 + h3) + a4.w;
            float mean = red8(v0+v1+v2+v3, gmask) * (1.f/32.f);
            float sq   = red8(v0*v0+v1*v1+v2*v2+v3*v3, gmask) * (1.f/32.f);
            float r = rsqrtf(sq - mean*mean + 1e-5f);
            ys[lr*33 + c0+0] = (v0-mean)*r*lg0 + lb0;
            ys[lr*33 + c0+1] = (v1-mean)*r*lg1 + lb1;
            ys[lr*33 + c0+2] = (v2-mean)*r*lg2 + lb2;
            ys[lr*33 + c0+3] = (v3-mean)*r*lg3 + lb3;
        }
    }
    __syncthreads();

    const float* yr = ys + t*33;
    float hv[32];
    #pragma unroll
    for (int i = 0; i < 32; i++) hv[i] = yr[i];
    float r = b2s[0];
    #pragma unroll
    for (int j = 0; j < 16; j++) {
        float s = b1[j];
        #pragma unroll
        for (int ci = 0; ci < 32; ci++) s += hv[ci] * w1[ci*16 + j];
        s = gelu_exact(s);
        r += s * w2[j];
    }
    out[base + t] = 1.f / (1.f + expf(-r));
}

// ---------------- launch ----------------
extern "C" void kernel_launch(void* const* d_in, const int* in_sizes, int n_in,
                              void* d_out, int out_size) {
    const float* x      = (const float*)d_in[0];
    const float* in_w   = (const float*)d_in[1];
    const float* in_b   = (const float*)d_in[2];
    const float* conv_w = (const float*)d_in[3];
    const float* bn_g   = (const float*)d_in[4];
    const float* bn_b   = (const float*)d_in[5];
    const float* qkv_w  = (const float*)d_in[6];
    const float* proj_w = (const float*)d_in[7];
    const float* proj_b = (const float*)d_in[8];
    const float* ln_g   = (const float*)d_in[9];
    const float* ln_b   = (const float*)d_in[10];
    const float* h1_w   = (const float*)d_in[11];
    const float* h1_b   = (const float*)d_in[12];
    const float* h2_w   = (const float*)d_in[13];
    const float* h2_b   = (const float*)d_in[14];
    float* out = (float*)d_out;

    cudaFuncSetAttribute(layer_pre,   cudaFuncAttributeMaxDynamicSharedMemorySize, PRE_SMEM_BYTES);
    cudaFuncSetAttribute(input_proj,  cudaFuncAttributeMaxDynamicSharedMemorySize, INP_SMEM_BYTES);
    cudaFuncSetAttribute(head_kernel, cudaFuncAttributeMaxDynamicSharedMemorySize, HEAD_SMEM_BYTES);

    input_proj<<<NROWS/256, 256, INP_SMEM_BYTES>>>(x, in_w, in_b);
    for (int l = 0; l < 4; l++) {
        layer_pre<<<BB, 512, PRE_SMEM_BYTES>>>(conv_w, qkv_w, proj_w, proj_b, ln_g, ln_b, l);
        bn_reduce<<<1, 1024>>>(bn_g, bn_b, l);
    }
    head_kernel<<<NROWS/512, 512, HEAD_SMEM_BYTES>>>(ln_g, ln_b, h1_w, h1_b, h2_w, h2_b, out);
}

// round 15
// speedup vs baseline: 1.0165x; 1.0165x over previous
#include <cuda_runtime.h>
#include <cuda_bf16.h>
#include <math.h>

#define BB   1024
#define FF   257
#define CC   32
#define QKV  96
#define QSP  100               // padded qs row stride
#define NROWS (BB*FF)          // 263168

typedef unsigned long long ull;

// ---------------- scratch (device globals; allocation-free) ----------------
__device__ float g_h   [(size_t)NROWS*CC];  // layer-0 input activations
__device__ float g_c   [(size_t)NROWS*CC];  // conv output per layer
__device__ float g_att [(size_t)NROWS*CC];  // attention branch per layer
__device__ float g_part[BB*64];             // per-CTA BN partial sums
__device__ float g_part2[64*64];            // stage-1 reduced partials
__device__ float g_stats[64];               // BN scale[32], shift[32]

__device__ __forceinline__ float gelu_exact(float v) {
    return 0.5f * v * (1.0f + erff(v * 0.70710678118654752f));
}
// 8-lane butterfly reduction with an explicit subgroup mask.
__device__ __forceinline__ float red8(float v, unsigned mask) {
    v += __shfl_xor_sync(mask, v, 1);
    v += __shfl_xor_sync(mask, v, 2);
    v += __shfl_xor_sync(mask, v, 4);
    return v;
}
// Blackwell packed fp32x2 FMA (PTX-only; 2x fp32 throughput).
__device__ __forceinline__ ull ffma2(ull a, ull b, ull c) {
    ull d;
    asm("fma.rn.f32x2 %0, %1, %2, %3;" : "=l"(d) : "l"(a), "l"(b), "l"(c));
    return d;
}
__device__ __forceinline__ ull pack2(float lo, float hi) {
    ull d; asm("mov.b64 %0, {%1, %2};" : "=l"(d) : "f"(lo), "f"(hi)); return d;
}
__device__ __forceinline__ float unpack_sum(ull v) {
    float lo, hi; asm("mov.b64 {%0, %1}, %2;" : "=f"(lo), "=f"(hi) : "l"(v));
    return lo + hi;
}

// ---------------- input projection: (B,F,18) @ (18,32) + b ----------------
#define INP_SMEM_FLOATS (576 + 32 + 256*19 + 256*33)
#define INP_SMEM_BYTES  (INP_SMEM_FLOATS*4)
__global__ __launch_bounds__(256) void input_proj(const float* __restrict__ x,
                                                  const float* __restrict__ in_w,
                                                  const float* __restrict__ in_b) {
    extern __shared__ float sm[];
    float* w  = sm;             // 18*32
    float* bv = w + 576;        // 32
    float* sx = bv + 32;        // 256*19 (pad 19)
    float* ys = sx + 256*19;    // 256*33 (pad 33)
    int t = threadIdx.x;
    for (int i = t; i < 576; i += 256) w[i] = in_w[i];
    if (t < 32) bv[t] = in_b[t];

    size_t base = (size_t)blockIdx.x * 256;
    const float* xg = x + base * 18;
    for (int i = t; i < 256*18; i += 256) sx[(i/18)*19 + (i%18)] = xg[i];
    __syncthreads();

    const float* xr = sx + t*19;
    float acc[32];
    #pragma unroll
    for (int co = 0; co < 32; co++) acc[co] = bv[co];
    #pragma unroll
    for (int i = 0; i < 18; i++) {
        float xv = xr[i];
        #pragma unroll
        for (int co = 0; co < 32; co++) acc[co] += xv * w[i*32 + co];
    }
    #pragma unroll
    for (int co = 0; co < 32; co++) ys[t*33 + co] = acc[co];
    __syncthreads();
    float* og = g_h + base * 32;
    for (int i = t; i < 256*32; i += 256) og[i] = ys[(i >> 5)*33 + (i & 31)];
}

// ---------------- per-layer heavy kernel (512 thr) ----------
#define PRE_SMEM_FLOATS ((FF+2)*CC + FF*QSP + 3*CC*CC + CC*QKV + CC*CC + CC + 64 + 64 + 1024)
#define PRE_SMEM_BYTES  (PRE_SMEM_FLOATS*4)

__global__ __launch_bounds__(512, 1) void layer_pre(const float* __restrict__ conv_w,
                                                    const float* __restrict__ qkv_w,
                                                    const float* __restrict__ proj_w,
                                                    const float* __restrict__ proj_b,
                                                    const float* __restrict__ ln_g,
                                                    const float* __restrict__ ln_b,
                                                    int l) {
    extern __shared__ float sm[];
    float* hp  = sm;                       // (FF+2)*32 padded activations
    float* qs  = hp + (FF+2)*CC;           // FF*QSP
    float* cw  = qs + FF*QSP;              // 3072
    float* qw  = cw + 3*CC*CC;             // 3072
    float* pw  = qw + CC*QKV;              // 1024
    float* pb  = pw + CC*CC;               // 32
    float* st  = pb + CC;                  // 64
    float* lgb = st + 64;                  // 64
    float* red = lgb + 64;                 // 1024

    const int b = blockIdx.x;
    const int t = threadIdx.x;

    // -------- weights + params --------
    for (int i = t; i < 3*CC*CC; i += 512) cw[i] = conv_w[l*3*CC*CC + i];
    for (int i = t; i < CC*QKV;  i += 512) qw[i] = qkv_w[l*CC*QKV + i];
    for (int i = t; i < CC*CC;   i += 512) pw[i] = proj_w[l*CC*CC + i];
    if (t < CC) pb[t] = proj_b[l*CC + t];
    if (l > 0) {
        if (t >= 64 && t < 128) st[t-64] = g_stats[t-64];
        if (t >= 128 && t < 160) lgb[t-128]      = ln_g[(l-1)*32 + (t-128)];
        if (t >= 160 && t < 192) lgb[32+(t-160)] = ln_b[(l-1)*32 + (t-160)];
    }
    if (t < CC) { hp[t] = 0.f; hp[(FF+1)*CC + t] = 0.f; }   // conv pad rows
    __syncthreads();

    // -------- load h into hp (fused post of layer l-1 when l>0) --------
    if (l == 0) {
        const float4* hrow = (const float4*)(g_h + (size_t)b * FF * CC);
        float4* hpd = (float4*)(hp + CC);
        for (int i = t; i < FF*8; i += 512) hpd[i] = hrow[i];
    } else {
        const float* cg0 = g_c   + (size_t)b * FF * CC;
        const float* ag0 = g_att + (size_t)b * FF * CC;
        int grp = t >> 3, ln8 = t & 7;               // 64 row-groups
        int c0 = ln8 * 4;
        unsigned gmask = 0xffu << ((t & 31) & 24);   // 8-lane subgroup mask
        float s0 = st[c0], s1 = st[c0+1], s2 = st[c0+2], s3 = st[c0+3];
        float h0 = st[32+c0], h1 = st[32+c0+1], h2 = st[32+c0+2], h3 = st[32+c0+3];
        float lg0 = lgb[c0], lg1 = lgb[c0+1], lg2 = lgb[c0+2], lg3 = lgb[c0+3];
        float lb0 = lgb[32+c0], lb1 = lgb[32+c0+1], lb2 = lgb[32+c0+2], lb3 = lgb[32+c0+3];

        // Batch-prefetch all 4 row pairs (rows 0..255 covered; row 256 tail below).
        float4 cA0, cA1, cA2, cA3, aA0, aA1, aA2, aA3;
        cA0 = *(const float4*)(cg0 + (grp      )*32 + c0);
        aA0 = *(const float4*)(ag0 + (grp      )*32 + c0);
        cA1 = *(const float4*)(cg0 + (grp +  64)*32 + c0);
        aA1 = *(const float4*)(ag0 + (grp +  64)*32 + c0);
        cA2 = *(const float4*)(cg0 + (grp + 128)*32 + c0);
        aA2 = *(const float4*)(ag0 + (grp + 128)*32 + c0);
        cA3 = *(const float4*)(cg0 + (grp + 192)*32 + c0);
        aA3 = *(const float4*)(ag0 + (grp + 192)*32 + c0);
        float4 cX, aX;
        if (grp == 0) {                              // tail row 256 (lanes 0-7 of warp 0)
            cX = *(const float4*)(cg0 + 256*32 + c0);
            aX = *(const float4*)(ag0 + 256*32 + c0);
        }

        #pragma unroll
        for (int i = 0; i < 4; i++) {
            float4 c4 = (i == 0) ? cA0 : (i == 1) ? cA1 : (i == 2) ? cA2 : cA3;
            float4 a4 = (i == 0) ? aA0 : (i == 1) ? aA1 : (i == 2) ? aA2 : aA3;
            int f = grp + i*64;
            float v0 = gelu_exact(c4.x*s0 + h0) + a4.x;
            float v1 = gelu_exact(c4.y*s1 + h1) + a4.y;
            float v2 = gelu_exact(c4.z*s2 + h2) + a4.z;
            float v3 = gelu_exact(c4.w*s3 + h3) + a4.w;
            float mean = red8(v0+v1+v2+v3, gmask) * (1.f/32.f);
            float sq   = red8(v0*v0+v1*v1+v2*v2+v3*v3, gmask) * (1.f/32.f);
            float r = rsqrtf(sq - mean*mean + 1e-5f);
            float4 o;
            o.x = (v0-mean)*r*lg0 + lb0;
            o.y = (v1-mean)*r*lg1 + lb1;
            o.z = (v2-mean)*r*lg2 + lb2;
            o.w = (v3-mean)*r*lg3 + lb3;
            *(float4*)(hp + (f+1)*32 + c0) = o;
        }
        if (grp == 0) {                              // row 256 compute
            float v0 = gelu_exact(cX.x*s0 + h0) + aX.x;
            float v1 = gelu_exact(cX.y*s1 + h1) + aX.y;
            float v2 = gelu_exact(cX.z*s2 + h2) + aX.z;
            float v3 = gelu_exact(cX.w*s3 + h3) + aX.w;
            float mean = red8(v0+v1+v2+v3, gmask) * (1.f/32.f);
            float sq   = red8(v0*v0+v1*v1+v2*v2+v3*v3, gmask) * (1.f/32.f);
            float r = rsqrtf(sq - mean*mean + 1e-5f);
            float4 o;
            o.x = (v0-mean)*r*lg0 + lb0;
            o.y = (v1-mean)*r*lg1 + lb1;
            o.z = (v2-mean)*r*lg2 + lb2;
            o.w = (v3-mean)*r*lg3 + lb3;
            *(float4*)(hp + 257*32 + c0) = o;
        }
    }
    __syncthreads();

    // -------- conv (width 3, SAME): 2 consecutive f per warp iteration -----
    {
        const int co = t & 31;
        const int fg = t >> 5;             // 16 warps
        ull w0p[16], w1p[16], w2p[16];
        #pragma unroll
        for (int j = 0; j < 16; j++) {
            w0p[j] = pack2(cw[       (2*j)*32 + co], cw[       (2*j+1)*32 + co]);
            w1p[j] = pack2(cw[1024 + (2*j)*32 + co], cw[1024 + (2*j+1)*32 + co]);
            w2p[j] = pack2(cw[2048 + (2*j)*32 + co], cw[2048 + (2*j+1)*32 + co]);
        }
        float ssum = 0.f, ssq = 0.f;
        float* cg = g_c + (size_t)b * FF * CC;
        for (int fp = fg; fp < 129; fp += 16) {      // f = 2*fp, 2*fp+1
            const int f = 2*fp;
            const float* r = hp + f*32;              // padded rows f-1..f+2
            ull aA0 = 0ull, aA1 = 0ull;              // output f
            ull aB0 = 0ull, aB1 = 0ull;              // output f+1
            #pragma unroll
            for (int q4 = 0; q4 < 8; q4++) {
                ulonglong2 m0 = *(const ulonglong2*)(r +      q4*4);
                ulonglong2 m1 = *(const ulonglong2*)(r + 32 + q4*4);
                ulonglong2 m2 = *(const ulonglong2*)(r + 64 + q4*4);
                ulonglong2 m3 = *(const ulonglong2*)(r + 96 + q4*4);
                if ((q4 & 1) == 0) {
                    aA0 = ffma2(m0.x, w0p[2*q4],   aA0);
                    aA0 = ffma2(m0.y, w0p[2*q4+1], aA0);
                    aA0 = ffma2(m1.x, w1p[2*q4],   aA0);
                    aA0 = ffma2(m1.y, w1p[2*q4+1], aA0);
                    aA0 = ffma2(m2.x, w2p[2*q4],   aA0);
                    aA0 = ffma2(m2.y, w2p[2*q4+1], aA0);
                    aB0 = ffma2(m1.x, w0p[2*q4],   aB0);
                    aB0 = ffma2(m1.y, w0p[2*q4+1], aB0);
                    aB0 = ffma2(m2.x, w1p[2*q4],   aB0);
                    aB0 = ffma2(m2.y, w1p[2*q4+1], aB0);
                    aB0 = ffma2(m3.x, w2p[2*q4],   aB0);
                    aB0 = ffma2(m3.y, w2p[2*q4+1], aB0);
                } else {
                    aA1 = ffma2(m0.x, w0p[2*q4],   aA1);
                    aA1 = ffma2(m0.y, w0p[2*q4+1], aA1);
                    aA1 = ffma2(m1.x, w1p[2*q4],   aA1);
                    aA1 = ffma2(m1.y, w1p[2*q4+1], aA1);
                    aA1 = ffma2(m2.x, w2p[2*q4],   aA1);
                    aA1 = ffma2(m2.y, w2p[2*q4+1], aA1);
                    aB1 = ffma2(m1.x, w0p[2*q4],   aB1);
                    aB1 = ffma2(m1.y, w0p[2*q4+1], aB1);
                    aB1 = ffma2(m2.x, w1p[2*q4],   aB1);
                    aB1 = ffma2(m2.y, w1p[2*q4+1], aB1);
                    aB1 = ffma2(m3.x, w2p[2*q4],   aB1);
                    aB1 = ffma2(m3.y, w2p[2*q4+1], aB1);
                }
            }
            float accA = unpack_sum(aA0) + unpack_sum(aA1);
            cg[f*32 + co] = accA;
            ssum += accA; ssq += accA*accA;
            if (f + 1 < FF) {
                float accB = unpack_sum(aB0) + unpack_sum(aB1);
                cg[(f+1)*32 + co] = accB;
                ssum += accB; ssq += accB*accB;
            }
        }
        red[      fg*32 + co] = ssum;
        red[512 + fg*32 + co] = ssq;
    }
    __syncthreads();
    if (t < 64) {
        float s = 0.f;
        int base = (t < 32) ? t : (512 + (t - 32));
        #pragma unroll
        for (int g = 0; g < 16; g++) s += red[base + g*32];
        g_part[b*64 + t] = s;
    }

    // -------- qkv: (F,32) @ (32,96) — one warp per row, 3 outputs/lane -----
    {
        const int co = t & 31;
        const int fg = t >> 5;             // 16 warps
        ull wa[16], wb[16], wc[16];
        #pragma unroll
        for (int j = 0; j < 16; j++) {
            wa[j] = pack2(qw[(2*j)*96 + co],      qw[(2*j+1)*96 + co]);
            wb[j] = pack2(qw[(2*j)*96 + co + 32], qw[(2*j+1)*96 + co + 32]);
            wc[j] = pack2(qw[(2*j)*96 + co + 64], qw[(2*j+1)*96 + co + 64]);
        }
        for (int f = fg; f < FF; f += 16) {
            const float* r = hp + (f+1)*32;
            ull a = 0ull, bq = 0ull, c = 0ull;
            #pragma unroll
            for (int q4 = 0; q4 < 8; q4++) {
                ulonglong2 m = *(const ulonglong2*)(r + q4*4);
                a  = ffma2(m.x, wa[2*q4],   a);
                a  = ffma2(m.y, wa[2*q4+1], a);
                bq = ffma2(m.x, wb[2*q4],   bq);
                bq = ffma2(m.y, wb[2*q4+1], bq);
                c  = ffma2(m.x, wc[2*q4],   c);
                c  = ffma2(m.y, wc[2*q4+1], c);
            }
            qs[f*QSP + co]      = unpack_sum(a);
            qs[f*QSP + co + 32] = unpack_sum(bq);
            qs[f*QSP + co + 64] = unpack_sum(c);
        }
    }
    __syncthreads();

    // -------- banded attention (window [f, f+2]) — float4 loads ------------
    for (int idx = t; idx < FF*4; idx += 512) {
        int f  = idx >> 2;
        int hh = idx & 3;
        float4 q0 = *(const float4*)(qs + f*QSP + hh*8);
        float4 q1 = *(const float4*)(qs + f*QSP + hh*8 + 4);
        int nv = min(FF-1, f+2) - f + 1;
        float sc[3];
        float m = -1e30f;
        #pragma unroll
        for (int jj = 0; jj < 3; jj++) {
            if (jj < nv) {
                int j = f + jj;
                float4 k0 = *(const float4*)(qs + j*QSP + 32 + hh*8);
                float4 k1 = *(const float4*)(qs + j*QSP + 32 + hh*8 + 4);
                float s = q0.x*k0.x + q0.y*k0.y + q0.z*k0.z + q0.w*k0.w
                        + q1.x*k1.x + q1.y*k1.y + q1.z*k1.z + q1.w*k1.w;
                s *= 0.35355339059327373f;
                sc[jj] = s;
                m = fmaxf(m, s);
            }
        }
        float e[3]; float den = 0.f;
        #pragma unroll
        for (int jj = 0; jj < 3; jj++)
            if (jj < nv) { e[jj] = expf(sc[jj] - m); den += e[jj]; }
        float inv = 1.f / den;
        float4 o0 = make_float4(0.f,0.f,0.f,0.f);
        float4 o1 = make_float4(0.f,0.f,0.f,0.f);
        #pragma unroll
        for (int jj = 0; jj < 3; jj++) {
            if (jj < nv) {
                float wj = e[jj] * inv;
                int j = f + jj;
                float4 v0 = *(const float4*)(qs + j*QSP + 64 + hh*8);
                float4 v1 = *(const float4*)(qs + j*QSP + 64 + hh*8 + 4);
                o0.x += wj*v0.x; o0.y += wj*v0.y; o0.z += wj*v0.z; o0.w += wj*v0.w;
                o1.x += wj*v1.x; o1.y += wj*v1.y; o1.z += wj*v1.z; o1.w += wj*v1.w;
            }
        }
        *(float4*)(qs + f*QSP + hh*8)     = o0;   // overwrite q slot
        *(float4*)(qs + f*QSP + hh*8 + 4) = o1;
    }
    __syncthreads();

    // -------- output projection: (F,32) @ (32,32) + b  [packed f32x2] ------
    {
        const int co = t & 31;
        const int fg = t >> 5;             // 16 groups
        ull wp[16];
        #pragma unroll
        for (int j = 0; j < 16; j++)
            wp[j] = pack2(pw[(2*j)*32 + co], pw[(2*j+1)*32 + co]);
        float bias = pb[co];
        float* ag = g_att + (size_t)b * FF * CC;
        for (int f = fg; f < FF; f += 16) {
            const float* r = qs + f*QSP;
            ull acc0 = 0ull, acc1 = 0ull;
            #pragma unroll
            for (int q4 = 0; q4 < 8; q4++) {
                ulonglong2 a = *(const ulonglong2*)(r + q4*4);
                acc0 = ffma2(a.x, wp[2*q4],   acc0);
                acc1 = ffma2(a.y, wp[2*q4+1], acc1);
            }
            ag[f*32 + co] = bias + unpack_sum(acc0) + unpack_sum(acc1);
        }
    }
}

// ---------------- BN stats: stage 1 (64 CTAs) ----------------
__global__ __launch_bounds__(256) void bn_reduce1() {
    __shared__ float sm[256];
    int t = threadIdx.x, g = blockIdx.x;
    int q = t & 63, sg = t >> 6;           // 4 subgroups
    float s = 0.f;
    for (int i = sg; i < 16; i += 4) s += g_part[(g*16 + i)*64 + q];
    sm[t] = s;
    __syncthreads();
    if (t < 64) g_part2[g*64 + t] = sm[t] + sm[64+t] + sm[128+t] + sm[192+t];
}

// ---------------- BN stats: stage 2 (1 CTA) ----------------
__global__ __launch_bounds__(256) void bn_reduce2(const float* __restrict__ bn_g,
                                                  const float* __restrict__ bn_b,
                                                  int l) {
    __shared__ float sm[256];
    int t = threadIdx.x;
    int q = t & 63, sg = t >> 6;           // 4 subgroups
    float s = 0.f;
    for (int i = sg; i < 64; i += 4) s += g_part2[i*64 + q];
    sm[t] = s;
    __syncthreads();
    if (t < 64) sm[t] = sm[t] + sm[64+t] + sm[128+t] + sm[192+t];
    __syncthreads();
    if (t < 32) {
        const float N = (float)NROWS;
        float mu  = sm[t] / N;
        float var = sm[32+t] / N - mu*mu;
        float scale = bn_g[l*32 + t] * rsqrtf(var + 1e-5f);
        g_stats[t]      = scale;
        g_stats[32 + t] = bn_b[l*32 + t] - mu*scale;
    }
}

// ---------------- fused: post(layer3) + head MLP ----------------
#define HEAD_SMEM_FLOATS (512*33 + 64 + 64 + 512 + 16 + 16 + 1)
#define HEAD_SMEM_BYTES  (HEAD_SMEM_FLOATS*4)
__global__ __launch_bounds__(512) void head_kernel(const float* __restrict__ ln_g,
                                                   const float* __restrict__ ln_b,
                                                   const float* __restrict__ h1_w,
                                                   const float* __restrict__ h1_b,
                                                   const float* __restrict__ h2_w,
                                                   const float* __restrict__ h2_b,
                                                   float* __restrict__ out) {
    extern __shared__ float sm[];
    float* ys  = sm;              // 512*33
    float* st  = ys + 512*33;     // 64
    float* lgb = st + 64;         // 64
    float* w1  = lgb + 64;        // 512
    float* b1  = w1 + 512;        // 16
    float* w2  = b1 + 16;         // 16
    float* b2s = w2 + 16;         // 1
    int t = threadIdx.x;
    if (t < 64)  st[t] = g_stats[t];
    if (t >= 64 && t < 96)   lgb[t-64]      = ln_g[3*32 + (t-64)];
    if (t >= 96 && t < 128)  lgb[32+(t-96)] = ln_b[3*32 + (t-96)];
    if (t >= 128 && t < 144) { b1[t-128] = h1_b[t-128]; w2[t-128] = h2_w[t-128]; }
    if (t == 144) b2s[0] = h2_b[0];
    for (int i = t; i < 512; i += 512) w1[i] = h1_w[i];
    __syncthreads();

    size_t base = (size_t)blockIdx.x * 512;
    const float* cg0 = g_c   + base * 32;
    const float* ag0 = g_att + base * 32;
    int grp = t >> 3, ln8 = t & 7;
    int c0 = ln8 * 4;
    unsigned gmask = 0xffu << ((t & 31) & 24);
    {
        float s0 = st[c0], s1 = st[c0+1], s2 = st[c0+2], s3 = st[c0+3];
        float h0 = st[32+c0], h1 = st[32+c0+1], h2 = st[32+c0+2], h3 = st[32+c0+3];
        float lg0 = lgb[c0], lg1 = lgb[c0+1], lg2 = lgb[c0+2], lg3 = lgb[c0+3];
        float lb0 = lgb[32+c0], lb1 = lgb[32+c0+1], lb2 = lgb[32+c0+2], lb3 = lgb[32+c0+3];
        #pragma unroll
        for (int it = 0; it < 8; it++) {
            int lr = grp + it*64;
            float4 c4 = *(const float4*)(cg0 + lr*32 + c0);
            float4 a4 = *(const float4*)(ag0 + lr*32 + c0);
            float v0 = gelu_exact(c4.x*s0 + h0) + a4.x;
            float v1 = gelu_exact(c4.y*s1 + h1) + a4.y;
            float v2 = gelu_exact(c4.z*s2 + h2) + a4.z;
            float v3 = gelu_exact(c4.w*s3 + h3) + a4.w;
            float mean = red8(v0+v1+v2+v3, gmask) * (1.f/32.f);
            float sq   = red8(v0*v0+v1*v1+v2*v2+v3*v3, gmask) * (1.f/32.f);
            float r = rsqrtf(sq - mean*mean + 1e-5f);
            ys[lr*33 + c0+0] = (v0-mean)*r*lg0 + lb0;
            ys[lr*33 + c0+1] = (v1-mean)*r*lg1 + lb1;
            ys[lr*33 + c0+2] = (v2-mean)*r*lg2 + lb2;
            ys[lr*33 + c0+3] = (v3-mean)*r*lg3 + lb3;
        }
    }
    __syncthreads();

    const float* yr = ys + t*33;
    float hv[32];
    #pragma unroll
    for (int i = 0; i < 32; i++) hv[i] = yr[i];
    float r = b2s[0];
    #pragma unroll
    for (int j = 0; j < 16; j++) {
        float s = b1[j];
        #pragma unroll
        for (int ci = 0; ci < 32; ci++) s += hv[ci] * w1[ci*16 + j];
        s = gelu_exact(s);
        r += s * w2[j];
    }
    out[base + t] = 1.f / (1.f + expf(-r));
}

// ---------------- launch ----------------
extern "C" void kernel_launch(void* const* d_in, const int* in_sizes, int n_in,
                              void* d_out, int out_size) {
    const float* x      = (const float*)d_in[0];
    const float* in_w   = (const float*)d_in[1];
    const float* in_b   = (const float*)d_in[2];
    const float* conv_w = (const float*)d_in[3];
    const float* bn_g   = (const float*)d_in[4];
    const float* bn_b   = (const float*)d_in[5];
    const float* qkv_w  = (const float*)d_in[6];
    const float* proj_w = (const float*)d_in[7];
    const float* proj_b = (const float*)d_in[8];
    const float* ln_g   = (const float*)d_in[9];
    const float* ln_b   = (const float*)d_in[10];
    const float* h1_w   = (const float*)d_in[11];
    const float* h1_b   = (const float*)d_in[12];
    const float* h2_w   = (const float*)d_in[13];
    const float* h2_b   = (const float*)d_in[14];
    float* out = (float*)d_out;

    cudaFuncSetAttribute(layer_pre,   cudaFuncAttributeMaxDynamicSharedMemorySize, PRE_SMEM_BYTES);
    cudaFuncSetAttribute(input_proj,  cudaFuncAttributeMaxDynamicSharedMemorySize, INP_SMEM_BYTES);
    cudaFuncSetAttribute(head_kernel, cudaFuncAttributeMaxDynamicSharedMemorySize, HEAD_SMEM_BYTES);

    input_proj<<<NROWS/256, 256, INP_SMEM_BYTES>>>(x, in_w, in_b);
    for (int l = 0; l < 4; l++) {
        layer_pre<<<BB, 512, PRE_SMEM_BYTES>>>(conv_w, qkv_w, proj_w, proj_b, ln_g, ln_b, l);
        bn_reduce1<<<64, 256>>>();
        bn_reduce2<<<1, 256>>>(bn_g, bn_b, l);
    }
    head_kernel<<<NROWS/512, 512, HEAD_SMEM_BYTES>>>(ln_g, ln_b, h1_w, h1_b, h2_w, h2_b, out);
}

// round 16
// speedup vs baseline: 1.0225x; 1.0059x over previous
#include <cuda_runtime.h>
#include <cuda_bf16.h>
#include <math.h>

#define BB   1024
#define FF   257
#define CC   32
#define QKV  96
#define QSP  100               // padded qs row stride
#define NROWS (BB*FF)          // 263168

typedef unsigned long long ull;

// ---------------- scratch (device globals; allocation-free) ----------------
__device__ float g_h   [(size_t)NROWS*CC];  // layer-0 input activations
__device__ float g_c   [(size_t)NROWS*CC];  // conv output per layer
__device__ float g_att [(size_t)NROWS*CC];  // attention branch per layer
__device__ float g_part[BB*64];             // per-CTA BN partial sums
__device__ float g_part2[64*64];            // stage-1 reduced partials

__device__ __forceinline__ float gelu_exact(float v) {
    return 0.5f * v * (1.0f + erff(v * 0.70710678118654752f));
}
// 8-lane butterfly reduction with an explicit subgroup mask.
__device__ __forceinline__ float red8(float v, unsigned mask) {
    v += __shfl_xor_sync(mask, v, 1);
    v += __shfl_xor_sync(mask, v, 2);
    v += __shfl_xor_sync(mask, v, 4);
    return v;
}
// Blackwell packed fp32x2 FMA (PTX-only; 2x fp32 throughput).
__device__ __forceinline__ ull ffma2(ull a, ull b, ull c) {
    ull d;
    asm("fma.rn.f32x2 %0, %1, %2, %3;" : "=l"(d) : "l"(a), "l"(b), "l"(c));
    return d;
}
__device__ __forceinline__ ull pack2(float lo, float hi) {
    ull d; asm("mov.b64 %0, {%1, %2};" : "=l"(d) : "f"(lo), "f"(hi)); return d;
}
__device__ __forceinline__ float unpack_sum(ull v) {
    float lo, hi; asm("mov.b64 {%0, %1}, %2;" : "=f"(lo), "=f"(hi) : "l"(v));
    return lo + hi;
}

// ---------------- input projection: (B,F,18) @ (18,32) + b ----------------
#define INP_SMEM_FLOATS (576 + 32 + 256*19 + 256*33)
#define INP_SMEM_BYTES  (INP_SMEM_FLOATS*4)
__global__ __launch_bounds__(256) void input_proj(const float* __restrict__ x,
                                                  const float* __restrict__ in_w,
                                                  const float* __restrict__ in_b) {
    extern __shared__ float sm[];
    float* w  = sm;             // 18*32
    float* bv = w + 576;        // 32
    float* sx = bv + 32;        // 256*19 (pad 19)
    float* ys = sx + 256*19;    // 256*33 (pad 33)
    int t = threadIdx.x;
    for (int i = t; i < 576; i += 256) w[i] = in_w[i];
    if (t < 32) bv[t] = in_b[t];

    size_t base = (size_t)blockIdx.x * 256;
    const float* xg = x + base * 18;
    for (int i = t; i < 256*18; i += 256) sx[(i/18)*19 + (i%18)] = xg[i];
    __syncthreads();

    const float* xr = sx + t*19;
    float acc[32];
    #pragma unroll
    for (int co = 0; co < 32; co++) acc[co] = bv[co];
    #pragma unroll
    for (int i = 0; i < 18; i++) {
        float xv = xr[i];
        #pragma unroll
        for (int co = 0; co < 32; co++) acc[co] += xv * w[i*32 + co];
    }
    #pragma unroll
    for (int co = 0; co < 32; co++) ys[t*33 + co] = acc[co];
    __syncthreads();
    float* og = g_h + base * 32;
    for (int i = t; i < 256*32; i += 256) og[i] = ys[(i >> 5)*33 + (i & 31)];
}

// ---------------- per-layer heavy kernel (512 thr) ----------
#define PRE_SMEM_FLOATS ((FF+2)*CC + FF*QSP + 3*CC*CC + CC*QKV + CC*CC + CC + 64 + 64 + 1024)
#define PRE_SMEM_BYTES  (PRE_SMEM_FLOATS*4)

__global__ __launch_bounds__(512, 1) void layer_pre(const float* __restrict__ conv_w,
                                                    const float* __restrict__ qkv_w,
                                                    const float* __restrict__ proj_w,
                                                    const float* __restrict__ proj_b,
                                                    const float* __restrict__ ln_g,
                                                    const float* __restrict__ ln_b,
                                                    const float* __restrict__ bn_g,
                                                    const float* __restrict__ bn_b,
                                                    int l) {
    extern __shared__ float sm[];
    float* hp  = sm;                       // (FF+2)*32 padded activations
    float* qs  = hp + (FF+2)*CC;           // FF*QSP
    float* cw  = qs + FF*QSP;              // 3072
    float* qw  = cw + 3*CC*CC;             // 3072
    float* pw  = qw + CC*QKV;              // 1024
    float* pb  = pw + CC*CC;               // 32
    float* st  = pb + CC;                  // 64
    float* lgb = st + 64;                  // 64
    float* red = lgb + 64;                 // 1024

    const int b = blockIdx.x;
    const int t = threadIdx.x;

    // -------- weights + params (+ in-kernel BN-stat finalize for l>0) ------
    for (int i = t; i < 3*CC*CC; i += 512) cw[i] = conv_w[l*3*CC*CC + i];
    for (int i = t; i < CC*QKV;  i += 512) qw[i] = qkv_w[l*CC*QKV + i];
    for (int i = t; i < CC*CC;   i += 512) pw[i] = proj_w[l*CC*CC + i];
    if (t < CC) pb[t] = proj_b[l*CC + t];
    if (l > 0) {
        if (t >= 128 && t < 160) lgb[t-128]      = ln_g[(l-1)*32 + (t-128)];
        if (t >= 160 && t < 192) lgb[32+(t-160)] = ln_b[(l-1)*32 + (t-160)];
        // reduce g_part2 (64x64, L2-hot) -> totals
        {
            int q = t & 63, sg = t >> 6;         // 8 groups
            float s = 0.f;
            #pragma unroll
            for (int i = 0; i < 8; i++) s += g_part2[(sg + i*8)*64 + q];
            red[sg*64 + q] = s;
        }
    }
    if (t < CC) { hp[t] = 0.f; hp[(FF+1)*CC + t] = 0.f; }   // conv pad rows
    __syncthreads();
    if (l > 0) {
        if (t < 64) {
            float acc = 0.f;
            #pragma unroll
            for (int g2 = 0; g2 < 8; g2++) acc += red[g2*64 + t];
            red[512 + t] = acc;
        }
        __syncthreads();
        if (t < 32) {
            const float N = (float)NROWS;
            float mu  = red[512 + t] / N;
            float var = red[512 + 32 + t] / N - mu*mu;
            float scale = bn_g[(l-1)*32 + t] * rsqrtf(var + 1e-5f);
            st[t]      = scale;
            st[32 + t] = bn_b[(l-1)*32 + t] - mu*scale;
        }
        __syncthreads();
    }

    // -------- load h into hp (fused post of layer l-1 when l>0) --------
    if (l == 0) {
        const float4* hrow = (const float4*)(g_h + (size_t)b * FF * CC);
        float4* hpd = (float4*)(hp + CC);
        for (int i = t; i < FF*8; i += 512) hpd[i] = hrow[i];
    } else {
        const float* cg0 = g_c   + (size_t)b * FF * CC;
        const float* ag0 = g_att + (size_t)b * FF * CC;
        int grp = t >> 3, ln8 = t & 7;               // 64 row-groups
        int c0 = ln8 * 4;
        unsigned gmask = 0xffu << ((t & 31) & 24);   // 8-lane subgroup mask
        float s0 = st[c0], s1 = st[c0+1], s2 = st[c0+2], s3 = st[c0+3];
        float h0 = st[32+c0], h1 = st[32+c0+1], h2 = st[32+c0+2], h3 = st[32+c0+3];
        float lg0 = lgb[c0], lg1 = lgb[c0+1], lg2 = lgb[c0+2], lg3 = lgb[c0+3];
        float lb0 = lgb[32+c0], lb1 = lgb[32+c0+1], lb2 = lgb[32+c0+2], lb3 = lgb[32+c0+3];

        // Batch-prefetch all 4 row pairs (rows 0..255; row 256 tail below).
        float4 cA0, cA1, cA2, cA3, aA0, aA1, aA2, aA3;
        cA0 = *(const float4*)(cg0 + (grp      )*32 + c0);
        aA0 = *(const float4*)(ag0 + (grp      )*32 + c0);
        cA1 = *(const float4*)(cg0 + (grp +  64)*32 + c0);
        aA1 = *(const float4*)(ag0 + (grp +  64)*32 + c0);
        cA2 = *(const float4*)(cg0 + (grp + 128)*32 + c0);
        aA2 = *(const float4*)(ag0 + (grp + 128)*32 + c0);
        cA3 = *(const float4*)(cg0 + (grp + 192)*32 + c0);
        aA3 = *(const float4*)(ag0 + (grp + 192)*32 + c0);
        float4 cX, aX;
        if (grp == 0) {                              // tail row 256
            cX = *(const float4*)(cg0 + 256*32 + c0);
            aX = *(const float4*)(ag0 + 256*32 + c0);
        }

        #pragma unroll
        for (int i = 0; i < 4; i++) {
            float4 c4 = (i == 0) ? cA0 : (i == 1) ? cA1 : (i == 2) ? cA2 : cA3;
            float4 a4 = (i == 0) ? aA0 : (i == 1) ? aA1 : (i == 2) ? aA2 : aA3;
            int f = grp + i*64;
            float v0 = gelu_exact(c4.x*s0 + h0) + a4.x;
            float v1 = gelu_exact(c4.y*s1 + h1) + a4.y;
            float v2 = gelu_exact(c4.z*s2 + h2) + a4.z;
            float v3 = gelu_exact(c4.w*s3 + h3) + a4.w;
            float mean = red8(v0+v1+v2+v3, gmask) * (1.f/32.f);
            float sq   = red8(v0*v0+v1*v1+v2*v2+v3*v3, gmask) * (1.f/32.f);
            float r = rsqrtf(sq - mean*mean + 1e-5f);
            float4 o;
            o.x = (v0-mean)*r*lg0 + lb0;
            o.y = (v1-mean)*r*lg1 + lb1;
            o.z = (v2-mean)*r*lg2 + lb2;
            o.w = (v3-mean)*r*lg3 + lb3;
            *(float4*)(hp + (f+1)*32 + c0) = o;
        }
        if (grp == 0) {                              // row 256 compute
            float v0 = gelu_exact(cX.x*s0 + h0) + aX.x;
            float v1 = gelu_exact(cX.y*s1 + h1) + aX.y;
            float v2 = gelu_exact(cX.z*s2 + h2) + aX.z;
            float v3 = gelu_exact(cX.w*s3 + h3) + aX.w;
            float mean = red8(v0+v1+v2+v3, gmask) * (1.f/32.f);
            float sq   = red8(v0*v0+v1*v1+v2*v2+v3*v3, gmask) * (1.f/32.f);
            float r = rsqrtf(sq - mean*mean + 1e-5f);
            float4 o;
            o.x = (v0-mean)*r*lg0 + lb0;
            o.y = (v1-mean)*r*lg1 + lb1;
            o.z = (v2-mean)*r*lg2 + lb2;
            o.w = (v3-mean)*r*lg3 + lb3;
            *(float4*)(hp + 257*32 + c0) = o;
        }
    }
    __syncthreads();

    // -------- conv (width 3, SAME): 2 consecutive f per warp iteration -----
    {
        const int co = t & 31;
        const int fg = t >> 5;             // 16 warps
        ull w0p[16], w1p[16], w2p[16];
        #pragma unroll
        for (int j = 0; j < 16; j++) {
            w0p[j] = pack2(cw[       (2*j)*32 + co], cw[       (2*j+1)*32 + co]);
            w1p[j] = pack2(cw[1024 + (2*j)*32 + co], cw[1024 + (2*j+1)*32 + co]);
            w2p[j] = pack2(cw[2048 + (2*j)*32 + co], cw[2048 + (2*j+1)*32 + co]);
        }
        float ssum = 0.f, ssq = 0.f;
        float* cg = g_c + (size_t)b * FF * CC;
        for (int fp = fg; fp < 129; fp += 16) {      // f = 2*fp, 2*fp+1
            const int f = 2*fp;
            const float* r = hp + f*32;              // padded rows f-1..f+2
            ull aA0 = 0ull, aA1 = 0ull;              // output f
            ull aB0 = 0ull, aB1 = 0ull;              // output f+1
            #pragma unroll
            for (int q4 = 0; q4 < 8; q4++) {
                ulonglong2 m0 = *(const ulonglong2*)(r +      q4*4);
                ulonglong2 m1 = *(const ulonglong2*)(r + 32 + q4*4);
                ulonglong2 m2 = *(const ulonglong2*)(r + 64 + q4*4);
                ulonglong2 m3 = *(const ulonglong2*)(r + 96 + q4*4);
                if ((q4 & 1) == 0) {
                    aA0 = ffma2(m0.x, w0p[2*q4],   aA0);
                    aA0 = ffma2(m0.y, w0p[2*q4+1], aA0);
                    aA0 = ffma2(m1.x, w1p[2*q4],   aA0);
                    aA0 = ffma2(m1.y, w1p[2*q4+1], aA0);
                    aA0 = ffma2(m2.x, w2p[2*q4],   aA0);
                    aA0 = ffma2(m2.y, w2p[2*q4+1], aA0);
                    aB0 = ffma2(m1.x, w0p[2*q4],   aB0);
                    aB0 = ffma2(m1.y, w0p[2*q4+1], aB0);
                    aB0 = ffma2(m2.x, w1p[2*q4],   aB0);
                    aB0 = ffma2(m2.y, w1p[2*q4+1], aB0);
                    aB0 = ffma2(m3.x, w2p[2*q4],   aB0);
                    aB0 = ffma2(m3.y, w2p[2*q4+1], aB0);
                } else {
                    aA1 = ffma2(m0.x, w0p[2*q4],   aA1);
                    aA1 = ffma2(m0.y, w0p[2*q4+1], aA1);
                    aA1 = ffma2(m1.x, w1p[2*q4],   aA1);
                    aA1 = ffma2(m1.y, w1p[2*q4+1], aA1);
                    aA1 = ffma2(m2.x, w2p[2*q4],   aA1);
                    aA1 = ffma2(m2.y, w2p[2*q4+1], aA1);
                    aB1 = ffma2(m1.x, w0p[2*q4],   aB1);
                    aB1 = ffma2(m1.y, w0p[2*q4+1], aB1);
                    aB1 = ffma2(m2.x, w1p[2*q4],   aB1);
                    aB1 = ffma2(m2.y, w1p[2*q4+1], aB1);
                    aB1 = ffma2(m3.x, w2p[2*q4],   aB1);
                    aB1 = ffma2(m3.y, w2p[2*q4+1], aB1);
                }
            }
            float accA = unpack_sum(aA0) + unpack_sum(aA1);
            cg[f*32 + co] = accA;
            ssum += accA; ssq += accA*accA;
            if (f + 1 < FF) {
                float accB = unpack_sum(aB0) + unpack_sum(aB1);
                cg[(f+1)*32 + co] = accB;
                ssum += accB; ssq += accB*accB;
            }
        }
        red[      fg*32 + co] = ssum;
        red[512 + fg*32 + co] = ssq;
    }
    __syncthreads();
    if (t < 64) {
        float s = 0.f;
        int base = (t < 32) ? t : (512 + (t - 32));
        #pragma unroll
        for (int g = 0; g < 16; g++) s += red[base + g*32];
        g_part[b*64 + t] = s;
    }

    // -------- qkv: (F,32) @ (32,96) — one warp per row, 3 outputs/lane -----
    {
        const int co = t & 31;
        const int fg = t >> 5;             // 16 warps
        ull wa[16], wb[16], wc[16];
        #pragma unroll
        for (int j = 0; j < 16; j++) {
            wa[j] = pack2(qw[(2*j)*96 + co],      qw[(2*j+1)*96 + co]);
            wb[j] = pack2(qw[(2*j)*96 + co + 32], qw[(2*j+1)*96 + co + 32]);
            wc[j] = pack2(qw[(2*j)*96 + co + 64], qw[(2*j+1)*96 + co + 64]);
        }
        for (int f = fg; f < FF; f += 16) {
            const float* r = hp + (f+1)*32;
            ull a = 0ull, bq = 0ull, c = 0ull;
            #pragma unroll
            for (int q4 = 0; q4 < 8; q4++) {
                ulonglong2 m = *(const ulonglong2*)(r + q4*4);
                a  = ffma2(m.x, wa[2*q4],   a);
                a  = ffma2(m.y, wa[2*q4+1], a);
                bq = ffma2(m.x, wb[2*q4],   bq);
                bq = ffma2(m.y, wb[2*q4+1], bq);
                c  = ffma2(m.x, wc[2*q4],   c);
                c  = ffma2(m.y, wc[2*q4+1], c);
            }
            qs[f*QSP + co]      = unpack_sum(a);
            qs[f*QSP + co + 32] = unpack_sum(bq);
            qs[f*QSP + co + 64] = unpack_sum(c);
        }
    }
    __syncthreads();

    // -------- banded attention (window [f, f+2]) — float4 loads ------------
    for (int idx = t; idx < FF*4; idx += 512) {
        int f  = idx >> 2;
        int hh = idx & 3;
        float4 q0 = *(const float4*)(qs + f*QSP + hh*8);
        float4 q1 = *(const float4*)(qs + f*QSP + hh*8 + 4);
        int nv = min(FF-1, f+2) - f + 1;
        float sc[3];
        float m = -1e30f;
        #pragma unroll
        for (int jj = 0; jj < 3; jj++) {
            if (jj < nv) {
                int j = f + jj;
                float4 k0 = *(const float4*)(qs + j*QSP + 32 + hh*8);
                float4 k1 = *(const float4*)(qs + j*QSP + 32 + hh*8 + 4);
                float s = q0.x*k0.x + q0.y*k0.y + q0.z*k0.z + q0.w*k0.w
                        + q1.x*k1.x + q1.y*k1.y + q1.z*k1.z + q1.w*k1.w;
                s *= 0.35355339059327373f;
                sc[jj] = s;
                m = fmaxf(m, s);
            }
        }
        float e[3]; float den = 0.f;
        #pragma unroll
        for (int jj = 0; jj < 3; jj++)
            if (jj < nv) { e[jj] = expf(sc[jj] - m); den += e[jj]; }
        float inv = 1.f / den;
        float4 o0 = make_float4(0.f,0.f,0.f,0.f);
        float4 o1 = make_float4(0.f,0.f,0.f,0.f);
        #pragma unroll
        for (int jj = 0; jj < 3; jj++) {
            if (jj < nv) {
                float wj = e[jj] * inv;
                int j = f + jj;
                float4 v0 = *(const float4*)(qs + j*QSP + 64 + hh*8);
                float4 v1 = *(const float4*)(qs + j*QSP + 64 + hh*8 + 4);
                o0.x += wj*v0.x; o0.y += wj*v0.y; o0.z += wj*v0.z; o0.w += wj*v0.w;
                o1.x += wj*v1.x; o1.y += wj*v1.y; o1.z += wj*v1.z; o1.w += wj*v1.w;
            }
        }
        *(float4*)(qs + f*QSP + hh*8)     = o0;   // overwrite q slot
        *(float4*)(qs + f*QSP + hh*8 + 4) = o1;
    }
    __syncthreads();

    // -------- output projection: (F,32) @ (32,32) + b  [packed f32x2] ------
    {
        const int co = t & 31;
        const int fg = t >> 5;             // 16 groups
        ull wp[16];
        #pragma unroll
        for (int j = 0; j < 16; j++)
            wp[j] = pack2(pw[(2*j)*32 + co], pw[(2*j+1)*32 + co]);
        float bias = pb[co];
        float* ag = g_att + (size_t)b * FF * CC;
        for (int f = fg; f < FF; f += 16) {
            const float* r = qs + f*QSP;
            ull acc0 = 0ull, acc1 = 0ull;
            #pragma unroll
            for (int q4 = 0; q4 < 8; q4++) {
                ulonglong2 a = *(const ulonglong2*)(r + q4*4);
                acc0 = ffma2(a.x, wp[2*q4],   acc0);
                acc1 = ffma2(a.y, wp[2*q4+1], acc1);
            }
            ag[f*32 + co] = bias + unpack_sum(acc0) + unpack_sum(acc1);
        }
    }
}

// ---------------- BN stats: stage 1 (64 CTAs) ----------------
__global__ __launch_bounds__(256) void bn_reduce1() {
    __shared__ float sm[256];
    int t = threadIdx.x, g = blockIdx.x;
    int q = t & 63, sg = t >> 6;           // 4 subgroups
    float s = 0.f;
    for (int i = sg; i < 16; i += 4) s += g_part[(g*16 + i)*64 + q];
    sm[t] = s;
    __syncthreads();
    if (t < 64) g_part2[g*64 + t] = sm[t] + sm[64+t] + sm[128+t] + sm[192+t];
}

// ---------------- fused: post(layer3) + head MLP ----------------
#define HEAD_SMEM_FLOATS (512*33 + 64 + 64 + 512 + 16 + 16 + 1)
#define HEAD_SMEM_BYTES  (HEAD_SMEM_FLOATS*4)
__global__ __launch_bounds__(512) void head_kernel(const float* __restrict__ ln_g,
                                                   const float* __restrict__ ln_b,
                                                   const float* __restrict__ bn_g,
                                                   const float* __restrict__ bn_b,
                                                   const float* __restrict__ h1_w,
                                                   const float* __restrict__ h1_b,
                                                   const float* __restrict__ h2_w,
                                                   const float* __restrict__ h2_b,
                                                   float* __restrict__ out) {
    extern __shared__ float sm[];
    float* ys  = sm;              // 512*33 (first 576 used as stats scratch)
    float* st  = ys + 512*33;     // 64
    float* lgb = st + 64;         // 64
    float* w1  = lgb + 64;        // 512
    float* b1  = w1 + 512;        // 16
    float* w2  = b1 + 16;         // 16
    float* b2s = w2 + 16;         // 1
    int t = threadIdx.x;
    if (t >= 64 && t < 96)   lgb[t-64]      = ln_g[3*32 + (t-64)];
    if (t >= 96 && t < 128)  lgb[32+(t-96)] = ln_b[3*32 + (t-96)];
    if (t >= 128 && t < 144) { b1[t-128] = h1_b[t-128]; w2[t-128] = h2_w[t-128]; }
    if (t == 144) b2s[0] = h2_b[0];
    for (int i = t; i < 512; i += 512) w1[i] = h1_w[i];
    // ---- finalize BN stats of layer 3 from g_part2 (ys as scratch) ----
    {
        int q = t & 63, sg = t >> 6;         // 8 groups
        float s = 0.f;
        #pragma unroll
        for (int i = 0; i < 8; i++) s += g_part2[(sg + i*8)*64 + q];
        ys[sg*64 + q] = s;
    }
    __syncthreads();
    if (t < 64) {
        float acc = 0.f;
        #pragma unroll
        for (int g2 = 0; g2 < 8; g2++) acc += ys[g2*64 + t];
        ys[512 + t] = acc;
    }
    __syncthreads();
    if (t < 32) {
        const float N = (float)NROWS;
        float mu  = ys[512 + t] / N;
        float var = ys[512 + 32 + t] / N - mu*mu;
        float scale = bn_g[3*32 + t] * rsqrtf(var + 1e-5f);
        st[t]      = scale;
        st[32 + t] = bn_b[3*32 + t] - mu*scale;
    }
    __syncthreads();

    size_t base = (size_t)blockIdx.x * 512;
    const float* cg0 = g_c   + base * 32;
    const float* ag0 = g_att + base * 32;
    int grp = t >> 3, ln8 = t & 7;
    int c0 = ln8 * 4;
    unsigned gmask = 0xffu << ((t & 31) & 24);
    {
        float s0 = st[c0], s1 = st[c0+1], s2 = st[c0+2], s3 = st[c0+3];
        float h0 = st[32+c0], h1 = st[32+c0+1], h2 = st[32+c0+2], h3 = st[32+c0+3];
        float lg0 = lgb[c0], lg1 = lgb[c0+1], lg2 = lgb[c0+2], lg3 = lgb[c0+3];
        float lb0 = lgb[32+c0], lb1 = lgb[32+c0+1], lb2 = lgb[32+c0+2], lb3 = lgb[32+c0+3];
        #pragma unroll
        for (int it = 0; it < 8; it++) {
            int lr = grp + it*64;
            float4 c4 = *(const float4*)(cg0 + lr*32 + c0);
            float4 a4 = *(const float4*)(ag0 + lr*32 + c0);
            float v0 = gelu_exact(c4.x*s0 + h0) + a4.x;
            float v1 = gelu_exact(c4.y*s1 + h1) + a4.y;
            float v2 = gelu_exact(c4.z*s2 + h2) + a4.z;
            float v3 = gelu_exact(c4.w*s3 + h3) + a4.w;
            float mean = red8(v0+v1+v2+v3, gmask) * (1.f/32.f);
            float sq   = red8(v0*v0+v1*v1+v2*v2+v3*v3, gmask) * (1.f/32.f);
            float r = rsqrtf(sq - mean*mean + 1e-5f);
            ys[lr*33 + c0+0] = (v0-mean)*r*lg0 + lb0;
            ys[lr*33 + c0+1] = (v1-mean)*r*lg1 + lb1;
            ys[lr*33 + c0+2] = (v2-mean)*r*lg2 + lb2;
            ys[lr*33 + c0+3] = (v3-mean)*r*lg3 + lb3;
        }
    }
    __syncthreads();

    const float* yr = ys + t*33;
    float hv[32];
    #pragma unroll
    for (int i = 0; i < 32; i++) hv[i] = yr[i];
    float r = b2s[0];
    #pragma unroll
    for (int j = 0; j < 16; j++) {
        float s = b1[j];
        #pragma unroll
        for (int ci = 0; ci < 32; ci++) s += hv[ci] * w1[ci*16 + j];
        s = gelu_exact(s);
        r += s * w2[j];
    }
    out[base + t] = 1.f / (1.f + expf(-r));
}

// ---------------- launch ----------------
extern "C" void kernel_launch(void* const* d_in, const int* in_sizes, int n_in,
                              void* d_out, int out_size) {
    const float* x      = (const float*)d_in[0];
    const float* in_w   = (const float*)d_in[1];
    const float* in_b   = (const float*)d_in[2];
    const float* conv_w = (const float*)d_in[3];
    const float* bn_g   = (const float*)d_in[4];
    const float* bn_b   = (const float*)d_in[5];
    const float* qkv_w  = (const float*)d_in[6];
    const float* proj_w = (const float*)d_in[7];
    const float* proj_b = (const float*)d_in[8];
    const float* ln_g   = (const float*)d_in[9];
    const float* ln_b   = (const float*)d_in[10];
    const float* h1_w   = (const float*)d_in[11];
    const float* h1_b   = (const float*)d_in[12];
    const float* h2_w   = (const float*)d_in[13];
    const float* h2_b   = (const float*)d_in[14];
    float* out = (float*)d_out;

    cudaFuncSetAttribute(layer_pre,   cudaFuncAttributeMaxDynamicSharedMemorySize, PRE_SMEM_BYTES);
    cudaFuncSetAttribute(input_proj,  cudaFuncAttributeMaxDynamicSharedMemorySize, INP_SMEM_BYTES);
    cudaFuncSetAttribute(head_kernel, cudaFuncAttributeMaxDynamicSharedMemorySize, HEAD_SMEM_BYTES);

    input_proj<<<NROWS/256, 256, INP_SMEM_BYTES>>>(x, in_w, in_b);
    for (int l = 0; l < 4; l++) {
        layer_pre<<<BB, 512, PRE_SMEM_BYTES>>>(conv_w, qkv_w, proj_w, proj_b,
                                               ln_g, ln_b, bn_g, bn_b, l);
        bn_reduce1<<<64, 256>>>();
    }
    head_kernel<<<NROWS/512, 512, HEAD_SMEM_BYTES>>>(ln_g, ln_b, bn_g, bn_b,
                                                     h1_w, h1_b, h2_w, h2_b, out);
}